// round 1
// baseline (speedup 1.0000x reference)
#include <cuda_runtime.h>

#define N_TOKENS  131072
#define NUM_CODES 1024
#define CODE_DIM  64
#define DECAY     0.99f
#define OMD       0.01f
#define EPS       1e-5f

// Output layout (f32, concatenated in reference return order)
#define OUT_Q     0
#define OUT_IDX   (N_TOKENS * CODE_DIM)        // 8388608
#define OUT_LOSS  (OUT_IDX + N_TOKENS)         // 8519680
#define OUT_CB    (OUT_LOSS + 1)               // 8519681
#define OUT_CS    (OUT_CB + NUM_CODES * CODE_DIM)  // 8585217
#define OUT_EMA   (OUT_CS + NUM_CODES)         // 8586241

// Scratch (device globals; no dynamic allocation allowed)
__device__ float g_dw[NUM_CODES * CODE_DIM];
__device__ float g_counts[NUM_CODES];
__device__ float g_cnorm[NUM_CODES];
__device__ float g_loss;

// ---------------- f32x2 packed-math helpers ----------------
__device__ __forceinline__ unsigned long long pk2(float x, float y) {
    unsigned long long r;
    asm("mov.b64 %0, {%1, %2};" : "=l"(r) : "f"(x), "f"(y));
    return r;
}
__device__ __forceinline__ void upk2(unsigned long long v, float& x, float& y) {
    asm("mov.b64 {%0, %1}, %2;" : "=f"(x), "=f"(y) : "l"(v));
}
__device__ __forceinline__ unsigned long long fma2(unsigned long long a,
                                                   unsigned long long b,
                                                   unsigned long long c) {
    unsigned long long r;
    asm("fma.rn.f32x2 %0, %1, %2, %3;" : "=l"(r) : "l"(a), "l"(b), "l"(c));
    return r;
}
__device__ __forceinline__ unsigned long long add2(unsigned long long a,
                                                   unsigned long long b) {
    unsigned long long r;
    asm("add.rn.f32x2 %0, %1, %2;" : "=l"(r) : "l"(a), "l"(b));
    return r;
}

// ---------------- prep: zero scratch + precompute ||c||^2 ----------------
__global__ void prep_kernel(const float4* __restrict__ cb4) {
    int i = blockIdx.x * 256 + threadIdx.x;   // 65536 threads total
    g_dw[i] = 0.0f;
    if (i < NUM_CODES) {
        g_counts[i] = 0.0f;
        float s = 0.0f;
        const float4* c = cb4 + i * 16;
#pragma unroll
        for (int j = 0; j < 16; j++) {
            float4 v = c[j];
            s += v.x * v.x + v.y * v.y + v.z * v.z + v.w * v.w;
        }
        g_cnorm[i] = s;
    }
    if (i == 0) g_loss = 0.0f;
}

// ---------------- main: assignment + quantized + scatter stats ----------------
// 256 threads/block, 2 tokens/thread (t and t+256), 512 tokens/block, 256 blocks.
// Codebook streamed through smem in 16 tiles of 64 codes, duplicated to f32x2
// pairs so one FFMA2 advances the dot products of BOTH tokens.
__global__ void __launch_bounds__(256, 1)
assign_kernel(const float4* __restrict__ z4, const float4* __restrict__ cb4,
              float* __restrict__ out) {
    __shared__ ulonglong2 tile[64 * 32];   // 64 codes x 64 dims (duplicated) = 32KB
    __shared__ float cns[64];
    __shared__ float red[256];

    const int tid  = threadIdx.x;
    const int base = blockIdx.x * 512;
    const int t0   = base + tid;
    const int t1   = t0 + 256;

    // Load both tokens, packed: zp[d] = (z0[d], z1[d])
    unsigned long long zp[64];
#pragma unroll
    for (int j = 0; j < 16; j++) {
        float4 a = z4[t0 * 16 + j];
        float4 b = z4[t1 * 16 + j];
        zp[4 * j + 0] = pk2(a.x, b.x);
        zp[4 * j + 1] = pk2(a.y, b.y);
        zp[4 * j + 2] = pk2(a.z, b.z);
        zp[4 * j + 3] = pk2(a.w, b.w);
    }
    // packed ||z||^2 for both tokens
    unsigned long long zn = 0ull;
#pragma unroll
    for (int d = 0; d < 64; d++) zn = fma2(zp[d], zp[d], zn);

    const unsigned long long NEG2 = pk2(-2.0f, -2.0f);

    float best0 = 3.0e38f, best1 = 3.0e38f;
    int   bi0 = 0, bi1 = 0;

    for (int t = 0; t < 16; t++) {
        const int kb = t * 64;
        __syncthreads();
        // cooperative tile load: 64 codes x 16 float4 = 1024 float4 loads
        for (int l = tid; l < 1024; l += 256) {
            int k = l >> 4;
            int j = l & 15;
            float4 v = cb4[(kb + k) * 16 + j];
            tile[k * 32 + 2 * j + 0] = make_ulonglong2(pk2(v.x, v.x), pk2(v.y, v.y));
            tile[k * 32 + 2 * j + 1] = make_ulonglong2(pk2(v.z, v.z), pk2(v.w, v.w));
        }
        if (tid < 64) cns[tid] = g_cnorm[kb + tid];
        __syncthreads();

        for (int k = 0; k < 64; k++) {
            const ulonglong2* row = &tile[k * 32];
            unsigned long long a0 = 0ull, a1 = 0ull, a2 = 0ull, a3 = 0ull;
#pragma unroll
            for (int i = 0; i < 32; i += 4) {
                ulonglong2 q0 = row[i + 0];
                ulonglong2 q1 = row[i + 1];
                ulonglong2 q2 = row[i + 2];
                ulonglong2 q3 = row[i + 3];
                a0 = fma2(zp[2 * i + 0], q0.x, a0);
                a1 = fma2(zp[2 * i + 1], q0.y, a1);
                a2 = fma2(zp[2 * i + 2], q1.x, a2);
                a3 = fma2(zp[2 * i + 3], q1.y, a3);
                a0 = fma2(zp[2 * i + 4], q2.x, a0);
                a1 = fma2(zp[2 * i + 5], q2.y, a1);
                a2 = fma2(zp[2 * i + 6], q3.x, a2);
                a3 = fma2(zp[2 * i + 7], q3.y, a3);
            }
            unsigned long long dot = add2(add2(a0, a1), add2(a2, a3));
            float cn = cns[k];
            unsigned long long sc = fma2(dot, NEG2, pk2(cn, cn));
            float s0, s1;
            upk2(sc, s0, s1);
            int kg = kb + k;
            if (s0 < best0) { best0 = s0; bi0 = kg; }
            if (s1 < best1) { best1 = s1; bi1 = kg; }
        }
    }

    // commitment-loss partial: d2min = ||z||^2 + (||c||^2 - 2 z.c)
    float zn0, zn1;
    upk2(zn, zn0, zn1);
    red[tid] = (zn0 + best0) + (zn1 + best1);
    __syncthreads();
    for (int s = 128; s > 0; s >>= 1) {
        if (tid < s) red[tid] += red[tid + s];
        __syncthreads();
    }
    if (tid == 0) atomicAdd(&g_loss, red[0]);

    // indices (as float, per assumed f32 output dtype)
    out[OUT_IDX + t0] = (float)bi0;
    out[OUT_IDX + t1] = (float)bi1;

    // quantized_st == codebook[idx] numerically (straight-through)
    float4* outq = (float4*)out;  // OUT_Q == 0
#pragma unroll
    for (int j = 0; j < 16; j++) {
        outq[t0 * 16 + j] = cb4[bi0 * 16 + j];
    }
#pragma unroll
    for (int j = 0; j < 16; j++) {
        outq[t1 * 16 + j] = cb4[bi1 * 16 + j];
    }

    // scatter stats
    atomicAdd(&g_counts[bi0], 1.0f);
    atomicAdd(&g_counts[bi1], 1.0f);
    float* dw0 = &g_dw[bi0 * 64];
    float* dw1 = &g_dw[bi1 * 64];
#pragma unroll
    for (int d = 0; d < 64; d++) {
        float z0d, z1d;
        upk2(zp[d], z0d, z1d);
        atomicAdd(&dw0[d], z0d);
        atomicAdd(&dw1[d], z1d);
    }
}

// ---------------- finalize: EMA updates + codebook normalize + loss ----------------
__global__ void finalize_kernel(const float* __restrict__ cs_in,
                                const float* __restrict__ ema_in,
                                float* __restrict__ out) {
    __shared__ float s[1024];
    int k = threadIdx.x;
    float ncs = DECAY * cs_in[k] + OMD * g_counts[k];
    s[k] = ncs;
    __syncthreads();
    for (int st = 512; st > 0; st >>= 1) {
        if (k < st) s[k] += s[k + st];
        __syncthreads();
    }
    float n   = s[0];
    float csk = (ncs + EPS) / (n + NUM_CODES * EPS) * n;
    out[OUT_CS + k] = ncs;
    float inv = 1.0f / csk;
#pragma unroll 4
    for (int d = 0; d < 64; d++) {
        float e = DECAY * ema_in[k * 64 + d] + OMD * g_dw[k * 64 + d];
        out[OUT_EMA + k * 64 + d] = e;
        out[OUT_CB + k * 64 + d]  = e * inv;
    }
    if (k == 0) out[OUT_LOSS] = g_loss * (1.0f / (float)(N_TOKENS * CODE_DIM));
}

extern "C" void kernel_launch(void* const* d_in, const int* in_sizes, int n_in,
                              void* d_out, int out_size) {
    const float* z   = (const float*)d_in[0];
    const float* cb  = (const float*)d_in[1];
    const float* cs  = (const float*)d_in[2];
    const float* ema = (const float*)d_in[3];
    float* out = (float*)d_out;

    prep_kernel<<<256, 256>>>((const float4*)cb);
    assign_kernel<<<256, 256>>>((const float4*)z, (const float4*)cb, out);
    finalize_kernel<<<1, 1024>>>(cs, ema, out);
}